// round 3
// baseline (speedup 1.0000x reference)
#include <cuda_runtime.h>

#define N_NODES 50000
#define N_EDGES 600000
#define D 128
#define D2 256
#define NLAYERS 5

// ---------------- scratch (static device memory; no allocations) -------------
__device__ float g_h[N_NODES * D];      // current node features
__device__ float g_z[N_NODES * D];      // z0 (pre-GEMM1), later y2 (post-GEMM2)
__device__ float g_y1[N_NODES * D2];    // GEMM1 output
__device__ float g_stats1[2 * D2];      // col sum / sumsq for BN1
__device__ float g_stats2[2 * D];       // col sum / sumsq for BN2
__device__ float g_scale1[D2], g_shift1[D2];
__device__ float g_scale2[D], g_shift2[D];

// ---------------- node embedding: h = sum_f atom_emb[f][x[:,f]] --------------
__global__ void embed_kernel(const int* __restrict__ x,
                             const float* __restrict__ atom_emb) {
    int idx = blockIdx.x * blockDim.x + threadIdx.x;
    int node = idx >> 5, lane = idx & 31;
    if (node >= N_NODES) return;
    const int* xr = x + node * 9;
    float4 acc = make_float4(0.f, 0.f, 0.f, 0.f);
#pragma unroll
    for (int f = 0; f < 9; f++) {
        int v = __ldg(xr + f);
        float4 t = ((const float4*)(atom_emb + (size_t)(f * 64 + v) * D))[lane];
        acc.x += t.x; acc.y += t.y; acc.z += t.z; acc.w += t.w;
    }
    ((float4*)(g_h + (size_t)node * D))[lane] = acc;
}

// ---------------- z = (1+eps)*h ; zero BN stat accumulators ------------------
__global__ void init_z_kernel(const float* __restrict__ eps_p, int l) {
    int idx = blockIdx.x * blockDim.x + threadIdx.x;
    if (idx < 2 * D2) g_stats1[idx] = 0.f;
    if (idx < 2 * D)  g_stats2[idx] = 0.f;
    if (idx >= N_NODES * (D / 4)) return;
    float s = 1.f + __ldg(eps_p + l);
    float4 v = ((const float4*)g_h)[idx];
    v.x *= s; v.y *= s; v.z *= s; v.w *= s;
    ((float4*)g_z)[idx] = v;
}

// ---------------- edge scatter: z[dst] += relu(h[src]+ea)*ew -----------------
__global__ void edge_kernel(const int* __restrict__ edge_index,
                            const int* __restrict__ edge_attr,
                            const float* __restrict__ edge_weight,
                            const float* __restrict__ bond_emb, int l) {
    __shared__ __align__(16) float sb[3 * 8 * D];
    const float* be = bond_emb + (size_t)l * 3 * 8 * D;
    for (int i = threadIdx.x; i < 3 * 8 * D; i += blockDim.x) sb[i] = be[i];
    __syncthreads();

    const int* src = edge_index;
    const int* dst = edge_index + N_EDGES;
    int gw = (blockIdx.x * blockDim.x + threadIdx.x) >> 5;
    int lane = threadIdx.x & 31;
    int nw = (gridDim.x * blockDim.x) >> 5;

    for (int e = gw; e < N_EDGES; e += nw) {
        int s = __ldg(src + e);
        int d = __ldg(dst + e);
        float w = __ldg(edge_weight + e);
        int a0 = __ldg(edge_attr + e * 3 + 0);
        int a1 = __ldg(edge_attr + e * 3 + 1);
        int a2 = __ldg(edge_attr + e * 3 + 2);
        float4 hv = ((const float4*)(g_h + (size_t)s * D))[lane];
        float4 e0 = ((const float4*)(sb + a0 * D))[lane];
        float4 e1 = ((const float4*)(sb + (8 + a1) * D))[lane];
        float4 e2 = ((const float4*)(sb + (16 + a2) * D))[lane];
        float4 m;
        m.x = fmaxf(hv.x + e0.x + e1.x + e2.x, 0.f) * w;
        m.y = fmaxf(hv.y + e0.y + e1.y + e2.y, 0.f) * w;
        m.z = fmaxf(hv.z + e0.z + e1.z + e2.z, 0.f) * w;
        m.w = fmaxf(hv.w + e0.w + e1.w + e2.w, 0.f) * w;
        atomicAdd(((float4*)(g_z + (size_t)d * D)) + lane, m);
    }
}

// ---------------- 128x128x16 tiled fp32 GEMM, 8x8 microtile, double-buffered -
// C[M x NOUT] = act(A)[M x K] @ W[K x NOUT] + bias, plus column sum/sumsq.
// act(a) = INBN ? relu(a*insc[k]+insh[k]) : a
template <int K, int NOUT, bool INBN>
__global__ __launch_bounds__(256, 2)
void gemm_kernel(const float* __restrict__ A, const float* __restrict__ W,
                 const float* __restrict__ bias, float* __restrict__ C,
                 const float* __restrict__ insc, const float* __restrict__ insh,
                 float* __restrict__ stats) {
    const int BM = 128, BN = 128, BK = 16;
    const int NT = K / BK;
    __shared__ __align__(16) float As[2][BK][BM];
    __shared__ __align__(16) float Bs[2][BK][BN];
    __shared__ float ssum[BN], ssq[BN];

    int tid = threadIdx.x;
    int lane = tid & 31, warp = tid >> 5;
    int wm = warp & 3, wn = warp >> 2;          // 4 warps along M, 2 along N
    int tm = lane >> 3, tn = lane & 7;          // 4 x 8 threads in warp
    int row0 = wm * 32 + tm * 4;                // rows row0..+3 and row0+16..+19
    int col0 = wn * 64 + tn * 4;                // cols col0..+3 and col0+32..+35

    int rowBase = blockIdx.y * BM;
    int colBase = blockIdx.x * BN;

    // global-load indices
    int arow = tid >> 1;                        // 0..127
    int akc  = (tid & 1) * 8;                   // 0 or 8
    int grow = rowBase + arow;
    int bcc  = lane * 4;                        // 0..124
    int bkr  = warp;                            // 0..7 (+8 second pass)

    float acc[8][8] = {};
    float4 ra0, ra1, rb0, rb1;

    // ---- prefetch helper (as lambda-free macro-style code) ----
    auto LOAD_TILE = [&](int kt) {
        float4 z4 = make_float4(0.f, 0.f, 0.f, 0.f);
        ra0 = z4; ra1 = z4;
        if (grow < N_NODES) {
            ra0 = *(const float4*)(A + (size_t)grow * K + kt + akc);
            ra1 = *(const float4*)(A + (size_t)grow * K + kt + akc + 4);
        }
        if (INBN) {
            float4 s0 = *(const float4*)(insc + kt + akc);
            float4 s1 = *(const float4*)(insc + kt + akc + 4);
            float4 h0 = *(const float4*)(insh + kt + akc);
            float4 h1 = *(const float4*)(insh + kt + akc + 4);
            ra0.x = fmaxf(fmaf(ra0.x, s0.x, h0.x), 0.f);
            ra0.y = fmaxf(fmaf(ra0.y, s0.y, h0.y), 0.f);
            ra0.z = fmaxf(fmaf(ra0.z, s0.z, h0.z), 0.f);
            ra0.w = fmaxf(fmaf(ra0.w, s0.w, h0.w), 0.f);
            ra1.x = fmaxf(fmaf(ra1.x, s1.x, h1.x), 0.f);
            ra1.y = fmaxf(fmaf(ra1.y, s1.y, h1.y), 0.f);
            ra1.z = fmaxf(fmaf(ra1.z, s1.z, h1.z), 0.f);
            ra1.w = fmaxf(fmaf(ra1.w, s1.w, h1.w), 0.f);
        }
        rb0 = *(const float4*)(W + (size_t)(kt + bkr) * NOUT + colBase + bcc);
        rb1 = *(const float4*)(W + (size_t)(kt + bkr + 8) * NOUT + colBase + bcc);
    };
    auto STORE_TILE = [&](int buf) {
        As[buf][akc + 0][arow] = ra0.x; As[buf][akc + 1][arow] = ra0.y;
        As[buf][akc + 2][arow] = ra0.z; As[buf][akc + 3][arow] = ra0.w;
        As[buf][akc + 4][arow] = ra1.x; As[buf][akc + 5][arow] = ra1.y;
        As[buf][akc + 6][arow] = ra1.z; As[buf][akc + 7][arow] = ra1.w;
        *(float4*)&Bs[buf][bkr][bcc]     = rb0;
        *(float4*)&Bs[buf][bkr + 8][bcc] = rb1;
    };

    LOAD_TILE(0);
    STORE_TILE(0);
    __syncthreads();

    int buf = 0;
#pragma unroll
    for (int t = 0; t < NT; t++) {
        if (t + 1 < NT) LOAD_TILE((t + 1) * BK);
#pragma unroll
        for (int k = 0; k < BK; k++) {
            float4 a0 = *(const float4*)&As[buf][k][row0];
            float4 a1 = *(const float4*)&As[buf][k][row0 + 16];
            float4 b0 = *(const float4*)&Bs[buf][k][col0];
            float4 b1 = *(const float4*)&Bs[buf][k][col0 + 32];
            float aa[8] = {a0.x, a0.y, a0.z, a0.w, a1.x, a1.y, a1.z, a1.w};
            float bb[8] = {b0.x, b0.y, b0.z, b0.w, b1.x, b1.y, b1.z, b1.w};
#pragma unroll
            for (int i = 0; i < 8; i++)
#pragma unroll
                for (int j = 0; j < 8; j++)
                    acc[i][j] = fmaf(aa[i], bb[j], acc[i][j]);
        }
        if (t + 1 < NT) {
            STORE_TILE(buf ^ 1);
            __syncthreads();
            buf ^= 1;
        }
    }

    // ---- epilogue: bias, store, per-column stats ----
    float bcol[8];
#pragma unroll
    for (int j = 0; j < 4; j++) {
        bcol[j]     = bias[colBase + col0 + j];
        bcol[4 + j] = bias[colBase + col0 + 32 + j];
    }

    if (tid < BN) { ssum[tid] = 0.f; ssq[tid] = 0.f; }
    float psum[8] = {}, psq[8] = {};
    __syncthreads();

#pragma unroll
    for (int i = 0; i < 8; i++) {
        int r = rowBase + row0 + (i < 4 ? i : 12 + i);   // i>=4 -> row0+16+(i-4)
        if (r < N_NODES) {
            float v[8];
#pragma unroll
            for (int j = 0; j < 8; j++) {
                v[j] = acc[i][j] + bcol[j];
                psum[j] += v[j];
                psq[j]  += v[j] * v[j];
            }
            *(float4*)(C + (size_t)r * NOUT + colBase + col0) =
                make_float4(v[0], v[1], v[2], v[3]);
            *(float4*)(C + (size_t)r * NOUT + colBase + col0 + 32) =
                make_float4(v[4], v[5], v[6], v[7]);
        }
    }
#pragma unroll
    for (int j = 0; j < 4; j++) {
        atomicAdd(&ssum[col0 + j], psum[j]);
        atomicAdd(&ssq[col0 + j], psq[j]);
        atomicAdd(&ssum[col0 + 32 + j], psum[4 + j]);
        atomicAdd(&ssq[col0 + 32 + j], psq[4 + j]);
    }
    __syncthreads();
    if (tid < BN) {
        atomicAdd(&stats[colBase + tid], ssum[tid]);
        atomicAdd(&stats[NOUT + colBase + tid], ssq[tid]);
    }
}

// ---------------- BN stats -> scale/shift ------------------------------------
__global__ void finalize_kernel(const float* __restrict__ stats,
                                const float* __restrict__ g, const float* __restrict__ b,
                                float* __restrict__ scale, float* __restrict__ shift, int C) {
    int c = threadIdx.x;
    if (c < C) {
        const float invn = 1.f / (float)N_NODES;
        float m = stats[c] * invn;
        float var = stats[C + c] * invn - m * m;
        float sc = g[c] * rsqrtf(var + 1e-5f);
        scale[c] = sc;
        shift[c] = b[c] - m * sc;
    }
}

// ---------------- apply BN2 (+ optional relu); write h or final output -------
__global__ void bn_apply_kernel(float* __restrict__ final_out, int relu, int to_out) {
    int idx = blockIdx.x * blockDim.x + threadIdx.x;
    if (idx >= N_NODES * (D / 4)) return;
    int c4 = idx & 31;
    float4 v = ((const float4*)g_z)[idx];
    float4 sc = ((const float4*)g_scale2)[c4];
    float4 sh = ((const float4*)g_shift2)[c4];
    v.x = fmaf(v.x, sc.x, sh.x);
    v.y = fmaf(v.y, sc.y, sh.y);
    v.z = fmaf(v.z, sc.z, sh.z);
    v.w = fmaf(v.w, sc.w, sh.w);
    if (relu) {
        v.x = fmaxf(v.x, 0.f); v.y = fmaxf(v.y, 0.f);
        v.z = fmaxf(v.z, 0.f); v.w = fmaxf(v.w, 0.f);
    }
    float4* dst = to_out ? (float4*)final_out : (float4*)g_h;
    dst[idx] = v;
}

// ---------------- launcher ---------------------------------------------------
extern "C" void kernel_launch(void* const* d_in, const int* in_sizes, int n_in,
                              void* d_out, int out_size) {
    const int*   x           = (const int*)d_in[0];
    const int*   edge_index  = (const int*)d_in[1];
    const int*   edge_attr   = (const int*)d_in[2];
    const float* edge_weight = (const float*)d_in[3];
    const float* atom_emb    = (const float*)d_in[4];
    const float* bond_emb    = (const float*)d_in[5];
    const float* W1          = (const float*)d_in[6];
    const float* b1          = (const float*)d_in[7];
    const float* bn1_g       = (const float*)d_in[8];
    const float* bn1_b       = (const float*)d_in[9];
    const float* W2          = (const float*)d_in[10];
    const float* b2          = (const float*)d_in[11];
    const float* eps_p       = (const float*)d_in[12];
    const float* bn_g        = (const float*)d_in[13];
    const float* bn_b        = (const float*)d_in[14];
    float* out = (float*)d_out;

    float *p_z, *p_y1, *p_sc1, *p_sh1, *p_st1, *p_st2, *p_sc2, *p_sh2;
    cudaGetSymbolAddress((void**)&p_z,   g_z);
    cudaGetSymbolAddress((void**)&p_y1,  g_y1);
    cudaGetSymbolAddress((void**)&p_sc1, g_scale1);
    cudaGetSymbolAddress((void**)&p_sh1, g_shift1);
    cudaGetSymbolAddress((void**)&p_st1, g_stats1);
    cudaGetSymbolAddress((void**)&p_st2, g_stats2);
    cudaGetSymbolAddress((void**)&p_sc2, g_scale2);
    cudaGetSymbolAddress((void**)&p_sh2, g_shift2);

    const int ELT_BLOCKS = (N_NODES * (D / 4) + 255) / 256;
    const int MB = (N_NODES + 127) / 128;

    embed_kernel<<<(N_NODES * 32 + 255) / 256, 256>>>(x, atom_emb);

    for (int l = 0; l < NLAYERS; l++) {
        init_z_kernel<<<ELT_BLOCKS, 256>>>(eps_p, l);
        edge_kernel<<<1184, 256>>>(edge_index, edge_attr, edge_weight, bond_emb, l);

        gemm_kernel<D, D2, false><<<dim3(D2 / 128, MB), 256>>>(
            p_z, W1 + (size_t)l * D * D2, b1 + (size_t)l * D2, p_y1,
            nullptr, nullptr, p_st1);
        finalize_kernel<<<1, 256>>>(p_st1, bn1_g + (size_t)l * D2, bn1_b + (size_t)l * D2,
                                    p_sc1, p_sh1, D2);

        gemm_kernel<D2, D, true><<<dim3(D / 128, MB), 256>>>(
            p_y1, W2 + (size_t)l * D2 * D, b2 + (size_t)l * D, p_z,
            p_sc1, p_sh1, p_st2);
        finalize_kernel<<<1, 128>>>(p_st2, bn_g + (size_t)l * D, bn_b + (size_t)l * D,
                                    p_sc2, p_sh2, D);

        int last = (l == NLAYERS - 1);
        bn_apply_kernel<<<ELT_BLOCKS, 256>>>(out, /*relu=*/!last, /*to_out=*/last);
    }
    (void)in_sizes; (void)n_in; (void)out_size;
}

// round 4
// speedup vs baseline: 1.5365x; 1.5365x over previous
#include <cuda_runtime.h>

#define N_NODES 50000
#define N_EDGES 600000
#define D 128
#define D2 256
#define NLAYERS 5

typedef unsigned long long ull;

// ---------------- scratch (static device memory; no allocations) -------------
__device__ float g_h[N_NODES * D];
__device__ float g_z[N_NODES * D];
__device__ float g_y1[N_NODES * D2];
__device__ float g_stats1[2 * D2];
__device__ float g_stats2[2 * D];
__device__ float g_scale1[D2], g_shift1[D2];
__device__ float g_scale2[D], g_shift2[D];

// ---------------- f32x2 packed helpers ---------------------------------------
__device__ __forceinline__ ull pack2(float lo, float hi) {
    ull r;
    asm("mov.b64 %0, {%1, %2};" : "=l"(r) : "f"(lo), "f"(hi));
    return r;
}
__device__ __forceinline__ void unpack2(ull v, float& lo, float& hi) {
    asm("mov.b64 {%0, %1}, %2;" : "=f"(lo), "=f"(hi) : "l"(v));
}
__device__ __forceinline__ void fma2(ull& acc, ull a, ull b) {
    asm("fma.rn.f32x2 %0, %1, %2, %0;" : "+l"(acc) : "l"(a), "l"(b));
}

// ---------------- node embedding ---------------------------------------------
__global__ void embed_kernel(const int* __restrict__ x,
                             const float* __restrict__ atom_emb) {
    int idx = blockIdx.x * blockDim.x + threadIdx.x;
    int node = idx >> 5, lane = idx & 31;
    if (node >= N_NODES) return;
    const int* xr = x + node * 9;
    float4 acc = make_float4(0.f, 0.f, 0.f, 0.f);
#pragma unroll
    for (int f = 0; f < 9; f++) {
        int v = __ldg(xr + f);
        float4 t = ((const float4*)(atom_emb + (size_t)(f * 64 + v) * D))[lane];
        acc.x += t.x; acc.y += t.y; acc.z += t.z; acc.w += t.w;
    }
    ((float4*)(g_h + (size_t)node * D))[lane] = acc;
}

// ---------------- z = (1+eps)*h ; zero BN stat accumulators ------------------
__global__ void init_z_kernel(const float* __restrict__ eps_p, int l) {
    int idx = blockIdx.x * blockDim.x + threadIdx.x;
    if (idx < 2 * D2) g_stats1[idx] = 0.f;
    if (idx < 2 * D)  g_stats2[idx] = 0.f;
    if (idx >= N_NODES * (D / 4)) return;
    float s = 1.f + __ldg(eps_p + l);
    float4 v = ((const float4*)g_h)[idx];
    v.x *= s; v.y *= s; v.z *= s; v.w *= s;
    ((float4*)g_z)[idx] = v;
}

// ---------------- edge scatter: z[dst] += relu(h[src]+ea)*ew -----------------
__global__ void edge_kernel(const int* __restrict__ edge_index,
                            const int* __restrict__ edge_attr,
                            const float* __restrict__ edge_weight,
                            const float* __restrict__ bond_emb, int l) {
    __shared__ __align__(16) float sb[3 * 8 * D];
    const float* be = bond_emb + (size_t)l * 3 * 8 * D;
    for (int i = threadIdx.x; i < 3 * 8 * D; i += blockDim.x) sb[i] = be[i];
    __syncthreads();

    const int* src = edge_index;
    const int* dst = edge_index + N_EDGES;
    int gw = (blockIdx.x * blockDim.x + threadIdx.x) >> 5;
    int lane = threadIdx.x & 31;
    int nw = (gridDim.x * blockDim.x) >> 5;

    for (int e = gw; e < N_EDGES; e += nw) {
        int s = __ldg(src + e);
        int d = __ldg(dst + e);
        float w = __ldg(edge_weight + e);
        int a0 = __ldg(edge_attr + e * 3 + 0);
        int a1 = __ldg(edge_attr + e * 3 + 1);
        int a2 = __ldg(edge_attr + e * 3 + 2);
        float4 hv = ((const float4*)(g_h + (size_t)s * D))[lane];
        float4 e0 = ((const float4*)(sb + a0 * D))[lane];
        float4 e1 = ((const float4*)(sb + (8 + a1) * D))[lane];
        float4 e2 = ((const float4*)(sb + (16 + a2) * D))[lane];
        float4 m;
        m.x = fmaxf(hv.x + e0.x + e1.x + e2.x, 0.f) * w;
        m.y = fmaxf(hv.y + e0.y + e1.y + e2.y, 0.f) * w;
        m.z = fmaxf(hv.z + e0.z + e1.z + e2.z, 0.f) * w;
        m.w = fmaxf(hv.w + e0.w + e1.w + e2.w, 0.f) * w;
        atomicAdd(((float4*)(g_z + (size_t)d * D)) + lane, m);
    }
}

// ---------------- 128x128x16 fp32 GEMM, 8x8 microtile via fma.rn.f32x2 -------
// C = act(A)[M x K] @ W[K x NOUT] + bias, plus column sum/sumsq stats.
template <int K, int NOUT, bool INBN>
__global__ __launch_bounds__(256, 2)
void gemm_kernel(const float* __restrict__ A, const float* __restrict__ W,
                 const float* __restrict__ bias, float* __restrict__ C,
                 const float* __restrict__ insc, const float* __restrict__ insh,
                 float* __restrict__ stats) {
    const int BM = 128, BN = 128, BK = 16;
    const int NT = K / BK;
    __shared__ __align__(16) float As[2][BK][BM];
    __shared__ __align__(16) float Bs[2][BK][BN];
    __shared__ float ssum[BN], ssq[BN];

    int tid = threadIdx.x;
    int lane = tid & 31, warp = tid >> 5;
    int wm = warp & 3, wn = warp >> 2;
    int tm = lane >> 3, tn = lane & 7;
    int row0 = wm * 32 + tm * 4;
    int col0 = wn * 64 + tn * 4;

    int rowBase = blockIdx.y * BM;
    int colBase = blockIdx.x * BN;

    int arow = tid >> 1;
    int akc  = (tid & 1) * 8;
    int grow = rowBase + arow;
    int bcc  = lane * 4;
    int bkr  = warp;

    // accumulators: 8 rows x 4 column-pairs (cols col0..+3, col0+32..+35)
    ull acc[8][4];
#pragma unroll
    for (int i = 0; i < 8; i++)
#pragma unroll
        for (int j = 0; j < 4; j++) acc[i][j] = 0ull;

    float4 ra0, ra1, rb0, rb1;

    auto LOAD_TILE = [&](int kt) {
        float4 z4 = make_float4(0.f, 0.f, 0.f, 0.f);
        ra0 = z4; ra1 = z4;
        if (grow < N_NODES) {
            ra0 = *(const float4*)(A + (size_t)grow * K + kt + akc);
            ra1 = *(const float4*)(A + (size_t)grow * K + kt + akc + 4);
        }
        if (INBN) {
            float4 s0 = *(const float4*)(insc + kt + akc);
            float4 s1 = *(const float4*)(insc + kt + akc + 4);
            float4 h0 = *(const float4*)(insh + kt + akc);
            float4 h1 = *(const float4*)(insh + kt + akc + 4);
            ra0.x = fmaxf(fmaf(ra0.x, s0.x, h0.x), 0.f);
            ra0.y = fmaxf(fmaf(ra0.y, s0.y, h0.y), 0.f);
            ra0.z = fmaxf(fmaf(ra0.z, s0.z, h0.z), 0.f);
            ra0.w = fmaxf(fmaf(ra0.w, s0.w, h0.w), 0.f);
            ra1.x = fmaxf(fmaf(ra1.x, s1.x, h1.x), 0.f);
            ra1.y = fmaxf(fmaf(ra1.y, s1.y, h1.y), 0.f);
            ra1.z = fmaxf(fmaf(ra1.z, s1.z, h1.z), 0.f);
            ra1.w = fmaxf(fmaf(ra1.w, s1.w, h1.w), 0.f);
        }
        rb0 = *(const float4*)(W + (size_t)(kt + bkr) * NOUT + colBase + bcc);
        rb1 = *(const float4*)(W + (size_t)(kt + bkr + 8) * NOUT + colBase + bcc);
    };
    auto STORE_TILE = [&](int buf) {
        As[buf][akc + 0][arow] = ra0.x; As[buf][akc + 1][arow] = ra0.y;
        As[buf][akc + 2][arow] = ra0.z; As[buf][akc + 3][arow] = ra0.w;
        As[buf][akc + 4][arow] = ra1.x; As[buf][akc + 5][arow] = ra1.y;
        As[buf][akc + 6][arow] = ra1.z; As[buf][akc + 7][arow] = ra1.w;
        *(float4*)&Bs[buf][bkr][bcc]     = rb0;
        *(float4*)&Bs[buf][bkr + 8][bcc] = rb1;
    };

    LOAD_TILE(0);
    STORE_TILE(0);
    __syncthreads();

    int buf = 0;
#pragma unroll 1
    for (int t = 0; t < NT; t++) {
        if (t + 1 < NT) LOAD_TILE((t + 1) * BK);
#pragma unroll
        for (int k = 0; k < BK; k++) {
            float4 a0 = *(const float4*)&As[buf][k][row0];
            float4 a1 = *(const float4*)&As[buf][k][row0 + 16];
            float4 b0 = *(const float4*)&Bs[buf][k][col0];
            float4 b1 = *(const float4*)&Bs[buf][k][col0 + 32];
            ull bv[4];
            bv[0] = pack2(b0.x, b0.y); bv[1] = pack2(b0.z, b0.w);
            bv[2] = pack2(b1.x, b1.y); bv[3] = pack2(b1.z, b1.w);
            float aa[8] = {a0.x, a0.y, a0.z, a0.w, a1.x, a1.y, a1.z, a1.w};
#pragma unroll
            for (int i = 0; i < 8; i++) {
                ull av = pack2(aa[i], aa[i]);
#pragma unroll
                for (int j = 0; j < 4; j++)
                    fma2(acc[i][j], av, bv[j]);
            }
        }
        if (t + 1 < NT) {
            STORE_TILE(buf ^ 1);
            __syncthreads();
            buf ^= 1;
        }
    }

    // ---- epilogue: bias, store, per-column stats ----
    float bcol[8];
#pragma unroll
    for (int j = 0; j < 4; j++) {
        bcol[j]     = bias[colBase + col0 + j];
        bcol[4 + j] = bias[colBase + col0 + 32 + j];
    }

    if (tid < BN) { ssum[tid] = 0.f; ssq[tid] = 0.f; }
    float psum[8] = {}, psq[8] = {};
    __syncthreads();

#pragma unroll
    for (int i = 0; i < 8; i++) {
        int r = rowBase + row0 + (i < 4 ? i : 12 + i);
        if (r < N_NODES) {
            float v[8];
            unpack2(acc[i][0], v[0], v[1]);
            unpack2(acc[i][1], v[2], v[3]);
            unpack2(acc[i][2], v[4], v[5]);
            unpack2(acc[i][3], v[6], v[7]);
#pragma unroll
            for (int j = 0; j < 8; j++) {
                v[j] += bcol[j];
                psum[j] += v[j];
                psq[j]  += v[j] * v[j];
            }
            *(float4*)(C + (size_t)r * NOUT + colBase + col0) =
                make_float4(v[0], v[1], v[2], v[3]);
            *(float4*)(C + (size_t)r * NOUT + colBase + col0 + 32) =
                make_float4(v[4], v[5], v[6], v[7]);
        }
    }
#pragma unroll
    for (int j = 0; j < 4; j++) {
        atomicAdd(&ssum[col0 + j], psum[j]);
        atomicAdd(&ssq[col0 + j], psq[j]);
        atomicAdd(&ssum[col0 + 32 + j], psum[4 + j]);
        atomicAdd(&ssq[col0 + 32 + j], psq[4 + j]);
    }
    __syncthreads();
    if (tid < BN) {
        atomicAdd(&stats[colBase + tid], ssum[tid]);
        atomicAdd(&stats[NOUT + colBase + tid], ssq[tid]);
    }
}

// ---------------- BN stats -> scale/shift ------------------------------------
__global__ void finalize_kernel(const float* __restrict__ stats,
                                const float* __restrict__ g, const float* __restrict__ b,
                                float* __restrict__ scale, float* __restrict__ shift, int C) {
    int c = threadIdx.x;
    if (c < C) {
        const float invn = 1.f / (float)N_NODES;
        float m = stats[c] * invn;
        float var = stats[C + c] * invn - m * m;
        float sc = g[c] * rsqrtf(var + 1e-5f);
        scale[c] = sc;
        shift[c] = b[c] - m * sc;
    }
}

// ---------------- apply BN2 (+ optional relu) --------------------------------
__global__ void bn_apply_kernel(float* __restrict__ final_out, int relu, int to_out) {
    int idx = blockIdx.x * blockDim.x + threadIdx.x;
    if (idx >= N_NODES * (D / 4)) return;
    int c4 = idx & 31;
    float4 v = ((const float4*)g_z)[idx];
    float4 sc = ((const float4*)g_scale2)[c4];
    float4 sh = ((const float4*)g_shift2)[c4];
    v.x = fmaf(v.x, sc.x, sh.x);
    v.y = fmaf(v.y, sc.y, sh.y);
    v.z = fmaf(v.z, sc.z, sh.z);
    v.w = fmaf(v.w, sc.w, sh.w);
    if (relu) {
        v.x = fmaxf(v.x, 0.f); v.y = fmaxf(v.y, 0.f);
        v.z = fmaxf(v.z, 0.f); v.w = fmaxf(v.w, 0.f);
    }
    float4* dst = to_out ? (float4*)final_out : (float4*)g_h;
    dst[idx] = v;
}

// ---------------- launcher ---------------------------------------------------
extern "C" void kernel_launch(void* const* d_in, const int* in_sizes, int n_in,
                              void* d_out, int out_size) {
    const int*   x           = (const int*)d_in[0];
    const int*   edge_index  = (const int*)d_in[1];
    const int*   edge_attr   = (const int*)d_in[2];
    const float* edge_weight = (const float*)d_in[3];
    const float* atom_emb    = (const float*)d_in[4];
    const float* bond_emb    = (const float*)d_in[5];
    const float* W1          = (const float*)d_in[6];
    const float* b1          = (const float*)d_in[7];
    const float* bn1_g       = (const float*)d_in[8];
    const float* bn1_b       = (const float*)d_in[9];
    const float* W2          = (const float*)d_in[10];
    const float* b2          = (const float*)d_in[11];
    const float* eps_p       = (const float*)d_in[12];
    const float* bn_g        = (const float*)d_in[13];
    const float* bn_b        = (const float*)d_in[14];
    float* out = (float*)d_out;

    float *p_z, *p_y1, *p_sc1, *p_sh1, *p_st1, *p_st2, *p_sc2, *p_sh2;
    cudaGetSymbolAddress((void**)&p_z,   g_z);
    cudaGetSymbolAddress((void**)&p_y1,  g_y1);
    cudaGetSymbolAddress((void**)&p_sc1, g_scale1);
    cudaGetSymbolAddress((void**)&p_sh1, g_shift1);
    cudaGetSymbolAddress((void**)&p_st1, g_stats1);
    cudaGetSymbolAddress((void**)&p_st2, g_stats2);
    cudaGetSymbolAddress((void**)&p_sc2, g_scale2);
    cudaGetSymbolAddress((void**)&p_sh2, g_shift2);

    const int ELT_BLOCKS = (N_NODES * (D / 4) + 255) / 256;
    const int MB = (N_NODES + 127) / 128;

    embed_kernel<<<(N_NODES * 32 + 255) / 256, 256>>>(x, atom_emb);

    for (int l = 0; l < NLAYERS; l++) {
        init_z_kernel<<<ELT_BLOCKS, 256>>>(eps_p, l);
        edge_kernel<<<1184, 256>>>(edge_index, edge_attr, edge_weight, bond_emb, l);

        gemm_kernel<D, D2, false><<<dim3(D2 / 128, MB), 256>>>(
            p_z, W1 + (size_t)l * D * D2, b1 + (size_t)l * D2, p_y1,
            nullptr, nullptr, p_st1);
        finalize_kernel<<<1, 256>>>(p_st1, bn1_g + (size_t)l * D2, bn1_b + (size_t)l * D2,
                                    p_sc1, p_sh1, D2);

        gemm_kernel<D2, D, true><<<dim3(D / 128, MB), 256>>>(
            p_y1, W2 + (size_t)l * D2 * D, b2 + (size_t)l * D, p_z,
            p_sc1, p_sh1, p_st2);
        finalize_kernel<<<1, 128>>>(p_st2, bn_g + (size_t)l * D, bn_b + (size_t)l * D,
                                    p_sc2, p_sh2, D);

        int last = (l == NLAYERS - 1);
        bn_apply_kernel<<<ELT_BLOCKS, 256>>>(out, /*relu=*/!last, /*to_out=*/last);
    }
    (void)in_sizes; (void)n_in; (void)out_size;
}